// round 1
// baseline (speedup 1.0000x reference)
#include <cuda_runtime.h>

// out[b] = sum_i cos(x[b,i]) * w[i] + bias
// x: [1048576, 32] f32 row-major. Each warp handles 4 rows (512B contiguous):
//   lane l -> float4 #l of the 4-row group; chunk = l&7 selects weight quad;
//   shfl_xor reduce within 8-lane groups; lanes with chunk==0 write 4 outputs/warp.

__global__ void __launch_bounds__(256) hybrid_regression_kernel(
    const float4* __restrict__ x4,
    const float*  __restrict__ w,
    const float*  __restrict__ bias,
    float*        __restrict__ out,
    int ngroups)                       // groups of 4 rows
{
    int gtid = blockIdx.x * blockDim.x + threadIdx.x;
    int warp = gtid >> 5;
    int lane = gtid & 31;
    if (warp >= ngroups) return;

    int chunk = lane & 7;    // which float4 within the row (0..7)

    // weight quad for this chunk (8 distinct lines, broadcast-friendly in L1)
    float4 wv = reinterpret_cast<const float4*>(w)[chunk];

    // one coalesced 512B load per warp: 4 rows x 32 floats
    float4 xv = x4[(size_t)warp * 32 + lane];

    float s = __cosf(xv.x) * wv.x
            + __cosf(xv.y) * wv.y
            + __cosf(xv.z) * wv.z
            + __cosf(xv.w) * wv.w;

    // reduce the 8 lanes that share a row
    s += __shfl_xor_sync(0xffffffffu, s, 1);
    s += __shfl_xor_sync(0xffffffffu, s, 2);
    s += __shfl_xor_sync(0xffffffffu, s, 4);

    if (chunk == 0) {
        int row = warp * 4 + (lane >> 3);
        out[row] = s + bias[0];
    }
}

extern "C" void kernel_launch(void* const* d_in, const int* in_sizes, int n_in,
                              void* d_out, int out_size)
{
    const float* x    = (const float*)d_in[0];   // [B, 32]
    // d_in[1] = theta: mathematically dead (RZ phase leaves <Z> unchanged)
    const float* w    = (const float*)d_in[2];   // [1, 32]
    const float* b    = (const float*)d_in[3];   // [1]
    float* out        = (float*)d_out;

    int batch   = in_sizes[0] / 32;              // rows
    int ngroups = batch / 4;                     // 4 rows per warp

    // 8 warps per block; one 4-row group per warp (no loop; occupancy hides latency)
    int threads = 256;
    int warps_per_block = threads / 32;
    int blocks = (ngroups + warps_per_block - 1) / warps_per_block;

    hybrid_regression_kernel<<<blocks, threads>>>(
        (const float4*)x, w, b, out, ngroups);
}

// round 2
// speedup vs baseline: 1.2534x; 1.2534x over previous
#include <cuda_runtime.h>

// out[b] = sum_i cos(x[b,i]) * w[i] + bias
// x: [B, 32] f32 row-major, B = 1048576.
//
// Layout: a "group" = 4 rows = 512B. Within a warp, lane l holds float4 #l of
// the group; chunk = l&7 selects the weight quad; a 3-step shfl_xor within each
// 8-lane subgroup produces the 4 row sums.
//
// Each warp owns GROUPS_PER_WARP=16 contiguous groups (8KB of x) and processes
// them 4 at a time with independent front-batched LDG.128 (MLP=4/thread).

#define GROUPS_PER_WARP 16

__device__ __forceinline__ float group_dot(const float4& xv, const float4& wv)
{
    return __cosf(xv.x) * wv.x + __cosf(xv.y) * wv.y
         + __cosf(xv.z) * wv.z + __cosf(xv.w) * wv.w;
}

__device__ __forceinline__ float reduce8(float s)
{
    s += __shfl_xor_sync(0xffffffffu, s, 1);
    s += __shfl_xor_sync(0xffffffffu, s, 2);
    s += __shfl_xor_sync(0xffffffffu, s, 4);
    return s;
}

__global__ void __launch_bounds__(256) hybrid_regression_kernel(
    const float4* __restrict__ x4,
    const float*  __restrict__ w,
    const float*  __restrict__ bias,
    float*        __restrict__ out,
    int ngroups)
{
    int gtid  = blockIdx.x * blockDim.x + threadIdx.x;
    int warp  = gtid >> 5;
    int lane  = gtid & 31;
    int chunk = lane & 7;
    int sub   = lane >> 3;          // which of the 4 rows in a group

    float4 wv = reinterpret_cast<const float4*>(w)[chunk];
    float  bb = bias[0];

    int g0 = warp * GROUPS_PER_WARP;
    if (g0 >= ngroups) return;

    const float4* base = x4 + (size_t)g0 * 32 + lane;

    if (g0 + GROUPS_PER_WARP <= ngroups) {
        #pragma unroll 1
        for (int it = 0; it < GROUPS_PER_WARP / 4; ++it) {
            // 4 independent 512B-coalesced loads (MLP=4)
            float4 xv0 = base[(it * 4 + 0) * 32];
            float4 xv1 = base[(it * 4 + 1) * 32];
            float4 xv2 = base[(it * 4 + 2) * 32];
            float4 xv3 = base[(it * 4 + 3) * 32];

            float s0 = reduce8(group_dot(xv0, wv));
            float s1 = reduce8(group_dot(xv1, wv));
            float s2 = reduce8(group_dot(xv2, wv));
            float s3 = reduce8(group_dot(xv3, wv));

            if (chunk == 0) {
                int r = (g0 + it * 4) * 4 + sub;   // rows for the 4 groups
                out[r +  0] = s0 + bb;
                out[r +  4] = s1 + bb;
                out[r +  8] = s2 + bb;
                out[r + 12] = s3 + bb;
            }
        }
    } else {
        // tail (not hit for B=1048576, kept for generality)
        for (int g = g0; g < ngroups; ++g) {
            float4 xv = x4[(size_t)g * 32 + lane];
            float s = reduce8(group_dot(xv, wv));
            if (chunk == 0) out[g * 4 + sub] = s + bb;
        }
    }
}

extern "C" void kernel_launch(void* const* d_in, const int* in_sizes, int n_in,
                              void* d_out, int out_size)
{
    const float* x    = (const float*)d_in[0];   // [B, 32]
    // d_in[1] = theta: mathematically dead (RZ phase leaves <Z> unchanged)
    const float* w    = (const float*)d_in[2];   // [1, 32]
    const float* b    = (const float*)d_in[3];   // [1]
    float* out        = (float*)d_out;

    int batch   = in_sizes[0] / 32;
    int ngroups = batch / 4;

    int threads = 256;
    int warps_per_block = threads / 32;
    int groups_per_block = warps_per_block * GROUPS_PER_WARP;   // 128
    int blocks = (ngroups + groups_per_block - 1) / groups_per_block;

    hybrid_regression_kernel<<<blocks, threads>>>(
        (const float4*)x, w, b, out, ngroups);
}

// round 3
// speedup vs baseline: 1.3061x; 1.0421x over previous
#include <cuda_runtime.h>

// out[b] = sum_i cos(x[b,i]) * w[i] + bias
// x: [B, 32] f32 row-major, B = 1048576.
//
// A "group" = 4 rows = 512B. Lane l holds float4 #l of the group; chunk = l&7
// selects the weight quad; 3-step shfl_xor within each 8-lane subgroup yields
// the 4 row sums. Each warp owns 16 contiguous groups, processed 4 at a time
// with a one-batch-deep software pipeline (next 4 LDG.128 issued before the
// current batch's MUFU/SHFL chain), streaming loads (__ldcs, evict-first).

#define GROUPS_PER_WARP 16
#define BATCH_GROUPS    4
#define NITER           (GROUPS_PER_WARP / BATCH_GROUPS)

__device__ __forceinline__ float group_dot(const float4& xv, const float4& wv)
{
    return __cosf(xv.x) * wv.x + __cosf(xv.y) * wv.y
         + __cosf(xv.z) * wv.z + __cosf(xv.w) * wv.w;
}

__device__ __forceinline__ float reduce8(float s)
{
    s += __shfl_xor_sync(0xffffffffu, s, 1);
    s += __shfl_xor_sync(0xffffffffu, s, 2);
    s += __shfl_xor_sync(0xffffffffu, s, 4);
    return s;
}

__global__ void __launch_bounds__(256) hybrid_regression_kernel(
    const float4* __restrict__ x4,
    const float*  __restrict__ w,
    const float*  __restrict__ bias,
    float*        __restrict__ out,
    int ngroups)
{
    int gtid  = blockIdx.x * blockDim.x + threadIdx.x;
    int warp  = gtid >> 5;
    int lane  = gtid & 31;
    int chunk = lane & 7;
    int sub   = lane >> 3;

    float4 wv = reinterpret_cast<const float4*>(w)[chunk];
    float  bb = bias[0];

    int g0 = warp * GROUPS_PER_WARP;
    if (g0 >= ngroups) return;

    const float4* base = x4 + (size_t)g0 * 32 + lane;

    if (g0 + GROUPS_PER_WARP <= ngroups) {
        // prologue: batch 0 in flight
        float4 c0 = __ldcs(base +   0);
        float4 c1 = __ldcs(base +  32);
        float4 c2 = __ldcs(base +  64);
        float4 c3 = __ldcs(base +  96);

        #pragma unroll 1
        for (int it = 0; it < NITER - 1; ++it) {
            // issue NEXT batch's loads before touching the current one
            const float4* nb = base + (size_t)(it + 1) * BATCH_GROUPS * 32;
            float4 n0 = __ldcs(nb +  0);
            float4 n1 = __ldcs(nb + 32);
            float4 n2 = __ldcs(nb + 64);
            float4 n3 = __ldcs(nb + 96);

            float s0 = reduce8(group_dot(c0, wv));
            float s1 = reduce8(group_dot(c1, wv));
            float s2 = reduce8(group_dot(c2, wv));
            float s3 = reduce8(group_dot(c3, wv));

            if (chunk == 0) {
                int r = (g0 + it * BATCH_GROUPS) * 4 + sub;
                out[r +  0] = s0 + bb;
                out[r +  4] = s1 + bb;
                out[r +  8] = s2 + bb;
                out[r + 12] = s3 + bb;
            }

            c0 = n0; c1 = n1; c2 = n2; c3 = n3;
        }

        // epilogue: last batch
        {
            float s0 = reduce8(group_dot(c0, wv));
            float s1 = reduce8(group_dot(c1, wv));
            float s2 = reduce8(group_dot(c2, wv));
            float s3 = reduce8(group_dot(c3, wv));

            if (chunk == 0) {
                int r = (g0 + (NITER - 1) * BATCH_GROUPS) * 4 + sub;
                out[r +  0] = s0 + bb;
                out[r +  4] = s1 + bb;
                out[r +  8] = s2 + bb;
                out[r + 12] = s3 + bb;
            }
        }
    } else {
        // tail (not hit for B=1048576, kept for generality)
        for (int g = g0; g < ngroups; ++g) {
            float4 xv = __ldcs(x4 + (size_t)g * 32 + lane);
            float s = reduce8(group_dot(xv, wv));
            if (chunk == 0) out[g * 4 + sub] = s + bb;
        }
    }
}

extern "C" void kernel_launch(void* const* d_in, const int* in_sizes, int n_in,
                              void* d_out, int out_size)
{
    const float* x    = (const float*)d_in[0];   // [B, 32]
    // d_in[1] = theta: mathematically dead (RZ phase leaves <Z> unchanged)
    const float* w    = (const float*)d_in[2];   // [1, 32]
    const float* b    = (const float*)d_in[3];   // [1]
    float* out        = (float*)d_out;

    int batch   = in_sizes[0] / 32;
    int ngroups = batch / 4;

    int threads = 256;
    int warps_per_block = threads / 32;
    int groups_per_block = warps_per_block * GROUPS_PER_WARP;   // 128
    int blocks = (ngroups + groups_per_block - 1) / groups_per_block;

    hybrid_regression_kernel<<<blocks, threads>>>(
        (const float4*)x, w, b, out, ngroups);
}